// round 11
// baseline (speedup 1.0000x reference)
#include <cuda_runtime.h>
#include <cuda_fp16.h>
#include <cstdint>

// ---------------- problem sizes ----------------
#define M_TOTAL 4096
#define K_TOTAL 4096
#define N_TOTAL 16384

#define BM 128
#define BN 128
#define BK 64
#define NKT (K_TOTAL / BK)            // 64 k-iterations

#define PITCH 144                     // bytes per smem row (128B data + 16B pad)
#define A_TILE_B (BM * PITCH)         // 18432
#define STAGE_BYTES (2 * A_TILE_B)    // A | B = 36864
#define STAGES 3
#define SMEM_TOTAL (STAGES * STAGE_BYTES)   // 110592 -> 2 CTAs/SM
// ---------------- scratch: converted operands ----------------
__device__ __half g_xh[(size_t)M_TOTAL * K_TOTAL];   // 32 MB
__device__ __half g_wh[(size_t)N_TOTAL * K_TOTAL];   // 128 MB

// ---------------- helpers ----------------
__device__ __forceinline__ uint32_t smem_u32(const void* p) {
    uint32_t a;
    asm("{ .reg .u64 t; cvta.to.shared.u64 t, %1; cvt.u32.u64 %0, t; }"
        : "=r"(a) : "l"(p));
    return a;
}
__device__ __forceinline__ void cp16(uint32_t dst, const void* src) {
    asm volatile("cp.async.cg.shared.global [%0], [%1], 16;" :: "r"(dst), "l"(src));
}
__device__ __forceinline__ void ldsm4(uint32_t* r, uint32_t a) {
    asm volatile("ldmatrix.sync.aligned.m8n8.x4.shared.b16 {%0,%1,%2,%3}, [%4];"
                 : "=r"(r[0]), "=r"(r[1]), "=r"(r[2]), "=r"(r[3]) : "r"(a));
}
__device__ __forceinline__ void mma16816(float* c, const uint32_t* a, const uint32_t* b) {
    asm volatile(
        "mma.sync.aligned.m16n8k16.row.col.f32.f16.f16.f32 "
        "{%0,%1,%2,%3}, {%4,%5,%6,%7}, {%8,%9}, {%0,%1,%2,%3};"
        : "+f"(c[0]), "+f"(c[1]), "+f"(c[2]), "+f"(c[3])
        : "r"(a[0]), "r"(a[1]), "r"(a[2]), "r"(a[3]), "r"(b[0]), "r"(b[1]));
}

// ---------------- pre-pass 1: x fp32 -> fp16 ----------------
__global__ void k_conv_x(const float* __restrict__ x) {
    size_t i = ((size_t)blockIdx.x * 256 + threadIdx.x) * 16;
    float f[16];
#pragma unroll
    for (int j = 0; j < 16; j += 4)
        *reinterpret_cast<float4*>(f + j) = *reinterpret_cast<const float4*>(x + i + j);
    __align__(16) __half2 h[8];
#pragma unroll
    for (int j = 0; j < 8; j++) h[j] = __floats2half2_rn(f[2 * j], f[2 * j + 1]);
    *reinterpret_cast<uint4*>(&g_xh[i])     = reinterpret_cast<uint4*>(h)[0];
    *reinterpret_cast<uint4*>(&g_xh[i + 8]) = reinterpret_cast<uint4*>(h)[1];
}

// ---------------- pre-pass 2: W int32 (harness-promoted int8) -> fp16 (exact) ----------------
__global__ void k_conv_w(const int* __restrict__ w) {
    size_t i = ((size_t)blockIdx.x * 256 + threadIdx.x) * 16;
    int v[16];
#pragma unroll
    for (int j = 0; j < 16; j += 4)
        *reinterpret_cast<int4*>(v + j) = *reinterpret_cast<const int4*>(w + i + j);
    __align__(16) __half h[16];
#pragma unroll
    for (int j = 0; j < 16; j++) h[j] = __int2half_rn(v[j]);
    *reinterpret_cast<uint4*>(&g_wh[i])     = reinterpret_cast<uint4*>(h)[0];
    *reinterpret_cast<uint4*>(&g_wh[i + 8]) = reinterpret_cast<uint4*>(h)[1];
}

// ---------------- main GEMM: 128x128 CTA, BK=64, 2 CTAs/SM, direct epilogue ----------------
__global__ void __launch_bounds__(256, 2) k_gemm(
    const float* __restrict__ sc, const float* __restrict__ bi,
    float* __restrict__ out)
{
    extern __shared__ __align__(16) char smem[];
    const uint32_t sb = smem_u32(smem);
    const int tid  = threadIdx.x;
    const int wid  = tid >> 5;
    const int lane = tid & 31;
    const int m0 = blockIdx.x * BM;    // M fastest -> x tiles L2-resident per wave
    const int n0 = blockIdx.y * BN;

    const int warp_m = (wid & 3) * 32; // 4 warps along M
    const int warp_n = (wid >> 2) * 64;// 2 warps along N

    // global->smem: row = tid/2, 64B half = tid%2; 4 cp16 per operand per thread
    const int r    = tid >> 1;
    const int half = tid & 1;
    const char* gA = (const char*)g_xh + (size_t)(m0 + r) * (K_TOTAL * 2) + half * 64;
    const char* gB = (const char*)g_wh + (size_t)(n0 + r) * (K_TOTAL * 2) + half * 64;
    const uint32_t so = (uint32_t)r * PITCH + half * 64;

    // ldmatrix lane offsets (validated fragment math; 128B data rows)
    const uint32_t aoff = (uint32_t)(lane & 15) * PITCH + (lane >> 4) * 16;
    const uint32_t boff = (uint32_t)((lane & 7) + ((lane >> 4) << 3)) * PITCH
                        + ((lane >> 3) & 1) * 16;

    float acc[2][8][4];
#pragma unroll
    for (int f = 0; f < 2; f++)
#pragma unroll
        for (int j = 0; j < 8; j++)
#pragma unroll
            for (int c = 0; c < 4; c++) acc[f][j][c] = 0.0f;

#define FILL(s, kt) do {                                                  \
        uint32_t a_ = sb + (uint32_t)(s) * STAGE_BYTES + so;              \
        size_t   o_ = (size_t)(kt) * 128;                                 \
        cp16(a_,                  gA + o_);                               \
        cp16(a_ + 16,             gA + o_ + 16);                          \
        cp16(a_ + 32,             gA + o_ + 32);                          \
        cp16(a_ + 48,             gA + o_ + 48);                          \
        uint32_t b_ = a_ + A_TILE_B;                                      \
        cp16(b_,                  gB + o_);                               \
        cp16(b_ + 16,             gB + o_ + 16);                          \
        cp16(b_ + 32,             gB + o_ + 32);                          \
        cp16(b_ + 48,             gB + o_ + 48);                          \
    } while (0)

    // prologue: stages 0..1
    FILL(0, 0);
    asm volatile("cp.async.commit_group;" ::: "memory");
    FILL(1, 1);
    asm volatile("cp.async.commit_group;" ::: "memory");

    int s = 0, sn = 2;   // current stage, next-fill stage (mod 3)
    for (int kt = 0; kt < NKT; kt++) {
        asm volatile("cp.async.wait_group %0;" :: "n"(STAGES - 2) : "memory");
        __syncthreads();

        if (kt + STAGES - 1 < NKT) {
            FILL(sn, kt + STAGES - 1);
        }
        asm volatile("cp.async.commit_group;" ::: "memory");

        const uint32_t stA = sb + (uint32_t)s * STAGE_BYTES;
        const uint32_t stB = stA + A_TILE_B;

#pragma unroll
        for (int h = 0; h < 4; h++) {              // four k16 sub-steps of BK=64
            uint32_t af[2][4], bq[4][4];
#pragma unroll
            for (int f = 0; f < 2; f++)
                ldsm4(af[f], stA + (uint32_t)(warp_m + 16 * f) * PITCH + aoff + h * 32);
#pragma unroll
            for (int g = 0; g < 4; g++)
                ldsm4(bq[g], stB + (uint32_t)(warp_n + 16 * g) * PITCH + boff + h * 32);
#pragma unroll
            for (int f = 0; f < 2; f++)
#pragma unroll
                for (int j = 0; j < 8; j++)
                    mma16816(acc[f][j], af[f], &bq[j >> 1][(j & 1) * 2]);
        }

        s = (s == 2) ? 0 : s + 1;
        sn = (sn == 2) ? 0 : sn + 1;
    }
#undef FILL

    // ---------------- epilogue: direct float2 stores, fused scale/bias ----------------
    // c-frag mapping: c0,c1 -> (row lane>>2, cols (lane&3)*2 + {0,1}); c2,c3 -> row+8
    float2 s2[8], b2[8];
#pragma unroll
    for (int j = 0; j < 8; j++) {
        const int n = n0 + warp_n + 8 * j + (lane & 3) * 2;
        s2[j] = *reinterpret_cast<const float2*>(sc + n);
        b2[j] = *reinterpret_cast<const float2*>(bi + n);
    }
#pragma unroll
    for (int f = 0; f < 2; f++) {
        const int row0 = m0 + warp_m + 16 * f + (lane >> 2);
#pragma unroll
        for (int j = 0; j < 8; j++) {
            const int n = n0 + warp_n + 8 * j + (lane & 3) * 2;
            float2 v0, v1;
            v0.x = fmaf(acc[f][j][0], s2[j].x, b2[j].x);
            v0.y = fmaf(acc[f][j][1], s2[j].y, b2[j].y);
            v1.x = fmaf(acc[f][j][2], s2[j].x, b2[j].x);
            v1.y = fmaf(acc[f][j][3], s2[j].y, b2[j].y);
            *reinterpret_cast<float2*>(out + (size_t)row0 * N_TOTAL + n)       = v0;
            *reinterpret_cast<float2*>(out + (size_t)(row0 + 8) * N_TOTAL + n) = v1;
        }
    }
}

// ---------------- launch ----------------
extern "C" void kernel_launch(void* const* d_in, const int* in_sizes, int n_in,
                              void* d_out, int out_size) {
    // x = 16777216 f32, qw = 67108864 int32 (promoted int8), scale/bias = 16384 each.
    int i_x = -1, big[2] = {-1, -1}, nbig = 0, smalls[2] = {-1, -1}, nsmall = 0;
    for (int i = 0; i < n_in; i++) {
        if (in_sizes[i] == 16777216) i_x = i;
        else if (in_sizes[i] == 67108864) { if (nbig < 2) big[nbig] = i; nbig++; }
        else { if (nsmall < 2) smalls[nsmall] = i; nsmall++; }
    }
    const float* x; const int* qw;
    if (i_x >= 0 && nbig >= 1) { x = (const float*)d_in[i_x]; qw = (const int*)d_in[big[0]]; }
    else if (nbig == 2)        { x = (const float*)d_in[big[0]]; qw = (const int*)d_in[big[1]]; }
    else                       { x = (const float*)d_in[0]; qw = (const int*)d_in[1]; }
    const float* scale = (nsmall >= 1) ? (const float*)d_in[smalls[0]] : (const float*)d_in[2];
    const float* bias  = (nsmall >= 2) ? (const float*)d_in[smalls[1]] : (const float*)d_in[3];
    float* out = (float*)d_out;

    k_conv_x<<<((size_t)M_TOTAL * K_TOTAL) / 16 / 256, 256>>>(x);
    k_conv_w<<<((size_t)N_TOTAL * K_TOTAL) / 16 / 256, 256>>>(qw);

    cudaFuncSetAttribute(k_gemm, cudaFuncAttributeMaxDynamicSharedMemorySize, SMEM_TOTAL);
    dim3 grid(M_TOTAL / BM, N_TOTAL / BN);   // (32, 128), M fastest
    k_gemm<<<grid, 256, SMEM_TOTAL>>>(scale, bias, out);
}

// round 12
// speedup vs baseline: 1.1404x; 1.1404x over previous
#include <cuda_runtime.h>
#include <cuda_fp16.h>
#include <cstdint>

// ---------------- problem sizes ----------------
#define M_TOTAL 4096
#define K_TOTAL 4096
#define N_TOTAL 16384

#define BM 128
#define BN 128
#define BK 32
#define NKT (K_TOTAL / BK)            // 128 k-iterations

#define PITCH 80                      // bytes per smem row (64B data + 16B pad)
#define A_TILE_B (BM * PITCH)         // 10240
#define STAGE_BYTES (2 * A_TILE_B)    // A | B = 20480
#define STAGES 4
#define SMEM_TOTAL (STAGES * STAGE_BYTES)   // 81920 -> 2 CTAs/SM

// ---------------- scratch: converted operands ----------------
__device__ __half g_xh[(size_t)M_TOTAL * K_TOTAL];   // 32 MB
__device__ __half g_wh[(size_t)N_TOTAL * K_TOTAL];   // 128 MB

// ---------------- helpers ----------------
__device__ __forceinline__ uint32_t smem_u32(const void* p) {
    uint32_t a;
    asm("{ .reg .u64 t; cvta.to.shared.u64 t, %1; cvt.u32.u64 %0, t; }"
        : "=r"(a) : "l"(p));
    return a;
}
__device__ __forceinline__ void cp16(uint32_t dst, const void* src) {
    asm volatile("cp.async.cg.shared.global [%0], [%1], 16;" :: "r"(dst), "l"(src));
}
__device__ __forceinline__ void ldsm4(uint32_t* r, uint32_t a) {
    asm volatile("ldmatrix.sync.aligned.m8n8.x4.shared.b16 {%0,%1,%2,%3}, [%4];"
                 : "=r"(r[0]), "=r"(r[1]), "=r"(r[2]), "=r"(r[3]) : "r"(a));
}
__device__ __forceinline__ void mma16816(float* c, const uint32_t* a, const uint32_t* b) {
    asm volatile(
        "mma.sync.aligned.m16n8k16.row.col.f32.f16.f16.f32 "
        "{%0,%1,%2,%3}, {%4,%5,%6,%7}, {%8,%9}, {%0,%1,%2,%3};"
        : "+f"(c[0]), "+f"(c[1]), "+f"(c[2]), "+f"(c[3])
        : "r"(a[0]), "r"(a[1]), "r"(a[2]), "r"(a[3]), "r"(b[0]), "r"(b[1]));
}

// ---------------- pre-pass 1: x fp32 -> fp16 ----------------
__global__ void k_conv_x(const float* __restrict__ x) {
    size_t i = ((size_t)blockIdx.x * 256 + threadIdx.x) * 16;
    float f[16];
#pragma unroll
    for (int j = 0; j < 16; j += 4)
        *reinterpret_cast<float4*>(f + j) = *reinterpret_cast<const float4*>(x + i + j);
    __align__(16) __half2 h[8];
#pragma unroll
    for (int j = 0; j < 8; j++) h[j] = __floats2half2_rn(f[2 * j], f[2 * j + 1]);
    *reinterpret_cast<uint4*>(&g_xh[i])     = reinterpret_cast<uint4*>(h)[0];
    *reinterpret_cast<uint4*>(&g_xh[i + 8]) = reinterpret_cast<uint4*>(h)[1];
}

// ---------------- pre-pass 2: W int32 (harness-promoted int8) -> fp16 (exact) ----------------
__global__ void k_conv_w(const int* __restrict__ w) {
    size_t i = ((size_t)blockIdx.x * 256 + threadIdx.x) * 16;
    int v[16];
#pragma unroll
    for (int j = 0; j < 16; j += 4)
        *reinterpret_cast<int4*>(v + j) = *reinterpret_cast<const int4*>(w + i + j);
    __align__(16) __half h[16];
#pragma unroll
    for (int j = 0; j < 16; j++) h[j] = __int2half_rn(v[j]);
    *reinterpret_cast<uint4*>(&g_wh[i])     = reinterpret_cast<uint4*>(h)[0];
    *reinterpret_cast<uint4*>(&g_wh[i + 8]) = reinterpret_cast<uint4*>(h)[1];
}

// ---------------- main GEMM: R10 mainloop + direct epilogue ----------------
__global__ void __launch_bounds__(256, 2) k_gemm(
    const float* __restrict__ sc, const float* __restrict__ bi,
    float* __restrict__ out)
{
    extern __shared__ __align__(16) char smem[];
    const uint32_t sb = smem_u32(smem);
    const int tid  = threadIdx.x;
    const int wid  = tid >> 5;
    const int lane = tid & 31;
    const int m0 = blockIdx.x * BM;    // M fastest -> x tiles L2-resident per wave
    const int n0 = blockIdx.y * BN;

    const int warp_m = (wid & 3) * 32; // 4 warps along M
    const int warp_n = (wid >> 2) * 64;// 2 warps along N

    // global->smem: row = tid/2, 32B half = tid%2; 2 cp16 per operand per thread
    const int r    = tid >> 1;
    const int half = tid & 1;
    const char* gA = (const char*)g_xh + (size_t)(m0 + r) * (K_TOTAL * 2) + half * 32;
    const char* gB = (const char*)g_wh + (size_t)(n0 + r) * (K_TOTAL * 2) + half * 32;
    const uint32_t so = (uint32_t)r * PITCH + half * 32;

    // ldmatrix lane offsets (validated fragment math)
    const uint32_t aoff = (uint32_t)(lane & 15) * PITCH + (lane >> 4) * 16;
    const uint32_t boff = (uint32_t)((lane & 7) + ((lane >> 4) << 3)) * PITCH
                        + ((lane >> 3) & 1) * 16;

    float acc[2][8][4];
#pragma unroll
    for (int f = 0; f < 2; f++)
#pragma unroll
        for (int j = 0; j < 8; j++)
#pragma unroll
            for (int c = 0; c < 4; c++) acc[f][j][c] = 0.0f;

#define FILL(s, kt) do {                                                  \
        uint32_t b_ = sb + (uint32_t)(s) * STAGE_BYTES + so;              \
        size_t   o_ = (size_t)(kt) * 64;                                  \
        cp16(b_,                gA + o_);                                 \
        cp16(b_ + 16,           gA + o_ + 16);                            \
        cp16(b_ + A_TILE_B,      gB + o_);                                \
        cp16(b_ + A_TILE_B + 16, gB + o_ + 16);                           \
    } while (0)

    // prologue: stages 0..2
#pragma unroll
    for (int p = 0; p < STAGES - 1; p++) {
        FILL(p, p);
        asm volatile("cp.async.commit_group;" ::: "memory");
    }

    for (int kt = 0; kt < NKT; kt++) {
        const int s = kt & (STAGES - 1);

        asm volatile("cp.async.wait_group %0;" :: "n"(STAGES - 2) : "memory");
        __syncthreads();

        if (kt + STAGES - 1 < NKT) {
            FILL((kt + STAGES - 1) & (STAGES - 1), kt + STAGES - 1);
        }
        asm volatile("cp.async.commit_group;" ::: "memory");

        const uint32_t stA = sb + (uint32_t)s * STAGE_BYTES;
        const uint32_t stB = stA + A_TILE_B;

#pragma unroll
        for (int h = 0; h < 2; h++) {              // two k16 halves of BK=32
            uint32_t af[2][4], bq[4][4];
#pragma unroll
            for (int f = 0; f < 2; f++)
                ldsm4(af[f], stA + (uint32_t)(warp_m + 16 * f) * PITCH + aoff + h * 32);
#pragma unroll
            for (int g = 0; g < 4; g++)
                ldsm4(bq[g], stB + (uint32_t)(warp_n + 16 * g) * PITCH + boff + h * 32);
#pragma unroll
            for (int f = 0; f < 2; f++)
#pragma unroll
                for (int j = 0; j < 8; j++)
                    mma16816(acc[f][j], af[f], &bq[j >> 1][(j & 1) * 2]);
        }
    }
#undef FILL

    // ---------------- epilogue: direct float2 stores, fused scale/bias ----------------
    // c-frag mapping: c0,c1 -> (row lane>>2, col (lane&3)*2 + {0,1}); c2,c3 -> row+8
    float2 s2[8], b2[8];
#pragma unroll
    for (int j = 0; j < 8; j++) {
        const int n = n0 + warp_n + 8 * j + (lane & 3) * 2;
        s2[j] = *reinterpret_cast<const float2*>(sc + n);
        b2[j] = *reinterpret_cast<const float2*>(bi + n);
    }
#pragma unroll
    for (int f = 0; f < 2; f++) {
        const int row0 = m0 + warp_m + 16 * f + (lane >> 2);
#pragma unroll
        for (int j = 0; j < 8; j++) {
            const int n = n0 + warp_n + 8 * j + (lane & 3) * 2;
            float2 v0, v1;
            v0.x = fmaf(acc[f][j][0], s2[j].x, b2[j].x);
            v0.y = fmaf(acc[f][j][1], s2[j].y, b2[j].y);
            v1.x = fmaf(acc[f][j][2], s2[j].x, b2[j].x);
            v1.y = fmaf(acc[f][j][3], s2[j].y, b2[j].y);
            *reinterpret_cast<float2*>(out + (size_t)row0 * N_TOTAL + n)       = v0;
            *reinterpret_cast<float2*>(out + (size_t)(row0 + 8) * N_TOTAL + n) = v1;
        }
    }
}

// ---------------- launch ----------------
extern "C" void kernel_launch(void* const* d_in, const int* in_sizes, int n_in,
                              void* d_out, int out_size) {
    // x = 16777216 f32, qw = 67108864 int32 (promoted int8), scale/bias = 16384 each.
    int i_x = -1, big[2] = {-1, -1}, nbig = 0, smalls[2] = {-1, -1}, nsmall = 0;
    for (int i = 0; i < n_in; i++) {
        if (in_sizes[i] == 16777216) i_x = i;
        else if (in_sizes[i] == 67108864) { if (nbig < 2) big[nbig] = i; nbig++; }
        else { if (nsmall < 2) smalls[nsmall] = i; nsmall++; }
    }
    const float* x; const int* qw;
    if (i_x >= 0 && nbig >= 1) { x = (const float*)d_in[i_x]; qw = (const int*)d_in[big[0]]; }
    else if (nbig == 2)        { x = (const float*)d_in[big[0]]; qw = (const int*)d_in[big[1]]; }
    else                       { x = (const float*)d_in[0]; qw = (const int*)d_in[1]; }
    const float* scale = (nsmall >= 1) ? (const float*)d_in[smalls[0]] : (const float*)d_in[2];
    const float* bias  = (nsmall >= 2) ? (const float*)d_in[smalls[1]] : (const float*)d_in[3];
    float* out = (float*)d_out;

    k_conv_x<<<((size_t)M_TOTAL * K_TOTAL) / 16 / 256, 256>>>(x);
    k_conv_w<<<((size_t)N_TOTAL * K_TOTAL) / 16 / 256, 256>>>(qw);

    cudaFuncSetAttribute(k_gemm, cudaFuncAttributeMaxDynamicSharedMemorySize, SMEM_TOTAL);
    dim3 grid(M_TOTAL / BM, N_TOTAL / BN);   // (32, 128), M fastest
    k_gemm<<<grid, 256, SMEM_TOTAL>>>(scale, bias, out);
}

// round 13
// speedup vs baseline: 1.1416x; 1.0010x over previous
#include <cuda_runtime.h>
#include <cuda_fp16.h>
#include <cstdint>

// ---------------- problem sizes ----------------
#define M_TOTAL 4096
#define K_TOTAL 4096
#define N_TOTAL 16384

#define BM 128
#define BN 128
#define BK 32
#define NKT (K_TOTAL / BK)            // 128 k-iterations

#define PITCH 80                      // bytes per smem row (64B data + 16B pad)
#define A_TILE_B (BM * PITCH)         // 10240
#define STAGE_BYTES (2 * A_TILE_B)    // A | B = 20480
#define STAGES 4
#define SMEM_TOTAL (STAGES * STAGE_BYTES)   // 81920 -> 2 CTAs/SM

// ---------------- scratch: converted operands ----------------
__device__ __half g_xh[(size_t)M_TOTAL * K_TOTAL];   // 32 MB
__device__ __half g_wh[(size_t)N_TOTAL * K_TOTAL];   // 128 MB

// ---------------- helpers ----------------
__device__ __forceinline__ uint32_t smem_u32(const void* p) {
    uint32_t a;
    asm("{ .reg .u64 t; cvta.to.shared.u64 t, %1; cvt.u32.u64 %0, t; }"
        : "=r"(a) : "l"(p));
    return a;
}
__device__ __forceinline__ void cp16(uint32_t dst, const void* src) {
    asm volatile("cp.async.cg.shared.global [%0], [%1], 16;" :: "r"(dst), "l"(src));
}
__device__ __forceinline__ void ldsm4(uint32_t* r, uint32_t a) {
    asm volatile("ldmatrix.sync.aligned.m8n8.x4.shared.b16 {%0,%1,%2,%3}, [%4];"
                 : "=r"(r[0]), "=r"(r[1]), "=r"(r[2]), "=r"(r[3]) : "r"(a));
}
__device__ __forceinline__ void mma16816(float* c, const uint32_t* a, const uint32_t* b) {
    asm volatile(
        "mma.sync.aligned.m16n8k16.row.col.f32.f16.f16.f32 "
        "{%0,%1,%2,%3}, {%4,%5,%6,%7}, {%8,%9}, {%0,%1,%2,%3};"
        : "+f"(c[0]), "+f"(c[1]), "+f"(c[2]), "+f"(c[3])
        : "r"(a[0]), "r"(a[1]), "r"(a[2]), "r"(a[3]), "r"(b[0]), "r"(b[1]));
}

// ---------------- pre-pass 1: x fp32 -> fp16 ----------------
__global__ void k_conv_x(const float* __restrict__ x) {
    size_t i = ((size_t)blockIdx.x * 256 + threadIdx.x) * 16;
    float f[16];
#pragma unroll
    for (int j = 0; j < 16; j += 4)
        *reinterpret_cast<float4*>(f + j) = *reinterpret_cast<const float4*>(x + i + j);
    __align__(16) __half2 h[8];
#pragma unroll
    for (int j = 0; j < 8; j++) h[j] = __floats2half2_rn(f[2 * j], f[2 * j + 1]);
    *reinterpret_cast<uint4*>(&g_xh[i])     = reinterpret_cast<uint4*>(h)[0];
    *reinterpret_cast<uint4*>(&g_xh[i + 8]) = reinterpret_cast<uint4*>(h)[1];
}

// ---------------- pre-pass 2: W int32 (harness-promoted int8) -> fp16 (exact) ----------------
__global__ void k_conv_w(const int* __restrict__ w) {
    size_t i = ((size_t)blockIdx.x * 256 + threadIdx.x) * 16;
    int v[16];
#pragma unroll
    for (int j = 0; j < 16; j += 4)
        *reinterpret_cast<int4*>(v + j) = *reinterpret_cast<const int4*>(w + i + j);
    __align__(16) __half h[16];
#pragma unroll
    for (int j = 0; j < 16; j++) h[j] = __int2half_rn(v[j]);
    *reinterpret_cast<uint4*>(&g_wh[i])     = reinterpret_cast<uint4*>(h)[0];
    *reinterpret_cast<uint4*>(&g_wh[i + 8]) = reinterpret_cast<uint4*>(h)[1];
}

// ---------------- main GEMM: R10 mainloop + direct epilogue ----------------
__global__ void __launch_bounds__(256, 2) k_gemm(
    const float* __restrict__ sc, const float* __restrict__ bi,
    float* __restrict__ out)
{
    extern __shared__ __align__(16) char smem[];
    const uint32_t sb = smem_u32(smem);
    const int tid  = threadIdx.x;
    const int wid  = tid >> 5;
    const int lane = tid & 31;
    const int m0 = blockIdx.x * BM;    // M fastest -> x tiles L2-resident per wave
    const int n0 = blockIdx.y * BN;

    const int warp_m = (wid & 3) * 32; // 4 warps along M
    const int warp_n = (wid >> 2) * 64;// 2 warps along N

    // global->smem: row = tid/2, 32B half = tid%2; 2 cp16 per operand per thread
    const int r    = tid >> 1;
    const int half = tid & 1;
    const char* gA = (const char*)g_xh + (size_t)(m0 + r) * (K_TOTAL * 2) + half * 32;
    const char* gB = (const char*)g_wh + (size_t)(n0 + r) * (K_TOTAL * 2) + half * 32;
    const uint32_t so = (uint32_t)r * PITCH + half * 32;

    // ldmatrix lane offsets (validated fragment math)
    const uint32_t aoff = (uint32_t)(lane & 15) * PITCH + (lane >> 4) * 16;
    const uint32_t boff = (uint32_t)((lane & 7) + ((lane >> 4) << 3)) * PITCH
                        + ((lane >> 3) & 1) * 16;

    float acc[2][8][4];
#pragma unroll
    for (int f = 0; f < 2; f++)
#pragma unroll
        for (int j = 0; j < 8; j++)
#pragma unroll
            for (int c = 0; c < 4; c++) acc[f][j][c] = 0.0f;

#define FILL(s, kt) do {                                                  \
        uint32_t b_ = sb + (uint32_t)(s) * STAGE_BYTES + so;              \
        size_t   o_ = (size_t)(kt) * 64;                                  \
        cp16(b_,                gA + o_);                                 \
        cp16(b_ + 16,           gA + o_ + 16);                            \
        cp16(b_ + A_TILE_B,      gB + o_);                                \
        cp16(b_ + A_TILE_B + 16, gB + o_ + 16);                           \
    } while (0)

    // prologue: stages 0..2
#pragma unroll
    for (int p = 0; p < STAGES - 1; p++) {
        FILL(p, p);
        asm volatile("cp.async.commit_group;" ::: "memory");
    }

    for (int kt = 0; kt < NKT; kt++) {
        const int s = kt & (STAGES - 1);

        asm volatile("cp.async.wait_group %0;" :: "n"(STAGES - 2) : "memory");
        __syncthreads();

        if (kt + STAGES - 1 < NKT) {
            FILL((kt + STAGES - 1) & (STAGES - 1), kt + STAGES - 1);
        }
        asm volatile("cp.async.commit_group;" ::: "memory");

        const uint32_t stA = sb + (uint32_t)s * STAGE_BYTES;
        const uint32_t stB = stA + A_TILE_B;

#pragma unroll
        for (int h = 0; h < 2; h++) {              // two k16 halves of BK=32
            uint32_t af[2][4], bq[4][4];
#pragma unroll
            for (int f = 0; f < 2; f++)
                ldsm4(af[f], stA + (uint32_t)(warp_m + 16 * f) * PITCH + aoff + h * 32);
#pragma unroll
            for (int g = 0; g < 4; g++)
                ldsm4(bq[g], stB + (uint32_t)(warp_n + 16 * g) * PITCH + boff + h * 32);
#pragma unroll
            for (int f = 0; f < 2; f++)
#pragma unroll
                for (int j = 0; j < 8; j++)
                    mma16816(acc[f][j], af[f], &bq[j >> 1][(j & 1) * 2]);
        }
    }
#undef FILL

    // ---------------- epilogue: direct float2 stores, fused scale/bias ----------------
    // c-frag mapping: c0,c1 -> (row lane>>2, col (lane&3)*2 + {0,1}); c2,c3 -> row+8
    float2 s2[8], b2[8];
#pragma unroll
    for (int j = 0; j < 8; j++) {
        const int n = n0 + warp_n + 8 * j + (lane & 3) * 2;
        s2[j] = *reinterpret_cast<const float2*>(sc + n);
        b2[j] = *reinterpret_cast<const float2*>(bi + n);
    }
#pragma unroll
    for (int f = 0; f < 2; f++) {
        const int row0 = m0 + warp_m + 16 * f + (lane >> 2);
#pragma unroll
        for (int j = 0; j < 8; j++) {
            const int n = n0 + warp_n + 8 * j + (lane & 3) * 2;
            float2 v0, v1;
            v0.x = fmaf(acc[f][j][0], s2[j].x, b2[j].x);
            v0.y = fmaf(acc[f][j][1], s2[j].y, b2[j].y);
            v1.x = fmaf(acc[f][j][2], s2[j].x, b2[j].x);
            v1.y = fmaf(acc[f][j][3], s2[j].y, b2[j].y);
            *reinterpret_cast<float2*>(out + (size_t)row0 * N_TOTAL + n)       = v0;
            *reinterpret_cast<float2*>(out + (size_t)(row0 + 8) * N_TOTAL + n) = v1;
        }
    }
}

// ---------------- launch ----------------
extern "C" void kernel_launch(void* const* d_in, const int* in_sizes, int n_in,
                              void* d_out, int out_size) {
    // x = 16777216 f32, qw = 67108864 int32 (promoted int8), scale/bias = 16384 each.
    int i_x = -1, big[2] = {-1, -1}, nbig = 0, smalls[2] = {-1, -1}, nsmall = 0;
    for (int i = 0; i < n_in; i++) {
        if (in_sizes[i] == 16777216) i_x = i;
        else if (in_sizes[i] == 67108864) { if (nbig < 2) big[nbig] = i; nbig++; }
        else { if (nsmall < 2) smalls[nsmall] = i; nsmall++; }
    }
    const float* x; const int* qw;
    if (i_x >= 0 && nbig >= 1) { x = (const float*)d_in[i_x]; qw = (const int*)d_in[big[0]]; }
    else if (nbig == 2)        { x = (const float*)d_in[big[0]]; qw = (const int*)d_in[big[1]]; }
    else                       { x = (const float*)d_in[0]; qw = (const int*)d_in[1]; }
    const float* scale = (nsmall >= 1) ? (const float*)d_in[smalls[0]] : (const float*)d_in[2];
    const float* bias  = (nsmall >= 2) ? (const float*)d_in[smalls[1]] : (const float*)d_in[3];
    float* out = (float*)d_out;

    k_conv_x<<<((size_t)M_TOTAL * K_TOTAL) / 16 / 256, 256>>>(x);
    k_conv_w<<<((size_t)N_TOTAL * K_TOTAL) / 16 / 256, 256>>>(qw);

    cudaFuncSetAttribute(k_gemm, cudaFuncAttributeMaxDynamicSharedMemorySize, SMEM_TOTAL);
    dim3 grid(M_TOTAL / BM, N_TOTAL / BN);   // (32, 128), M fastest
    k_gemm<<<grid, 256, SMEM_TOTAL>>>(scale, bias, out);
}

// round 14
// speedup vs baseline: 1.2286x; 1.0762x over previous
#include <cuda_runtime.h>
#include <cuda_fp16.h>
#include <cstdint>

// ---------------- problem sizes ----------------
#define M_TOTAL 4096
#define K_TOTAL 4096
#define N_TOTAL 16384

#define BM 128
#define BN 128
#define BK 32
#define NKT (K_TOTAL / BK)            // 128 k-iterations

#define PITCH 80                      // bytes per smem row (64B data + 16B pad)
#define A_TILE_B (BM * PITCH)         // 10240
#define STAGE_BYTES (2 * A_TILE_B)    // A | B = 20480
#define STAGES 4
#define SMEM_TOTAL (STAGES * STAGE_BYTES)   // 81920 -> 2 CTAs/SM (>= epilogue 67584)
#define LDC 132                       // epilogue f32 staging pitch

// ---------------- scratch: converted operands ----------------
__device__ __half g_xh[(size_t)M_TOTAL * K_TOTAL];   // 32 MB
__device__ __half g_wh[(size_t)N_TOTAL * K_TOTAL];   // 128 MB

// ---------------- helpers ----------------
__device__ __forceinline__ uint32_t smem_u32(const void* p) {
    uint32_t a;
    asm("{ .reg .u64 t; cvta.to.shared.u64 t, %1; cvt.u32.u64 %0, t; }"
        : "=r"(a) : "l"(p));
    return a;
}
__device__ __forceinline__ void cp16(uint32_t dst, const void* src) {
    asm volatile("cp.async.cg.shared.global [%0], [%1], 16;" :: "r"(dst), "l"(src));
}
__device__ __forceinline__ void ldsm4(uint32_t* r, uint32_t a) {
    asm volatile("ldmatrix.sync.aligned.m8n8.x4.shared.b16 {%0,%1,%2,%3}, [%4];"
                 : "=r"(r[0]), "=r"(r[1]), "=r"(r[2]), "=r"(r[3]) : "r"(a));
}
__device__ __forceinline__ void mma16816(float* c, const uint32_t* a, const uint32_t* b) {
    asm volatile(
        "mma.sync.aligned.m16n8k16.row.col.f32.f16.f16.f32 "
        "{%0,%1,%2,%3}, {%4,%5,%6,%7}, {%8,%9}, {%0,%1,%2,%3};"
        : "+f"(c[0]), "+f"(c[1]), "+f"(c[2]), "+f"(c[3])
        : "r"(a[0]), "r"(a[1]), "r"(a[2]), "r"(a[3]), "r"(b[0]), "r"(b[1]));
}

// ---------------- merged pre-pass: x fp32->fp16, W int32->fp16 (exact) ----------------
#define XBLOCKS ((M_TOTAL * (size_t)K_TOTAL) / 16 / 256)          // 4096
#define WBLOCKS ((N_TOTAL * (size_t)K_TOTAL) / 16 / 256)          // 16384
__global__ void k_conv(const float* __restrict__ x, const int* __restrict__ w) {
    const int b = blockIdx.x;
    if (b < (int)XBLOCKS) {
        size_t i = ((size_t)b * 256 + threadIdx.x) * 16;
        float f[16];
#pragma unroll
        for (int j = 0; j < 16; j += 4)
            *reinterpret_cast<float4*>(f + j) = *reinterpret_cast<const float4*>(x + i + j);
        __align__(16) __half2 h[8];
#pragma unroll
        for (int j = 0; j < 8; j++) h[j] = __floats2half2_rn(f[2 * j], f[2 * j + 1]);
        *reinterpret_cast<uint4*>(&g_xh[i])     = reinterpret_cast<uint4*>(h)[0];
        *reinterpret_cast<uint4*>(&g_xh[i + 8]) = reinterpret_cast<uint4*>(h)[1];
    } else {
        size_t i = ((size_t)(b - XBLOCKS) * 256 + threadIdx.x) * 16;
        int v[16];
#pragma unroll
        for (int j = 0; j < 16; j += 4)
            *reinterpret_cast<int4*>(v + j) = *reinterpret_cast<const int4*>(w + i + j);
        __align__(16) __half h[16];
#pragma unroll
        for (int j = 0; j < 16; j++) h[j] = __int2half_rn(v[j]);
        *reinterpret_cast<uint4*>(&g_wh[i])     = reinterpret_cast<uint4*>(h)[0];
        *reinterpret_cast<uint4*>(&g_wh[i + 8]) = reinterpret_cast<uint4*>(h)[1];
    }
}

// ---------------- main GEMM: 128x128 CTA, 2 CTAs/SM, hand mma.sync (R10 mainloop) ----------------
__global__ void __launch_bounds__(256, 2) k_gemm(
    const float* __restrict__ sc, const float* __restrict__ bi,
    float* __restrict__ out)
{
    extern __shared__ __align__(16) char smem[];
    const uint32_t sb = smem_u32(smem);
    const int tid  = threadIdx.x;
    const int wid  = tid >> 5;
    const int lane = tid & 31;
    const int m0 = blockIdx.x * BM;    // M fastest -> x tiles L2-resident per wave
    const int n0 = blockIdx.y * BN;

    const int warp_m = (wid & 3) * 32; // 4 warps along M
    const int warp_n = (wid >> 2) * 64;// 2 warps along N

    // global->smem: row = tid/2, 32B half = tid%2; 2 cp16 per operand per thread
    const int r    = tid >> 1;
    const int half = tid & 1;
    const char* gA = (const char*)g_xh + (size_t)(m0 + r) * (K_TOTAL * 2) + half * 32;
    const char* gB = (const char*)g_wh + (size_t)(n0 + r) * (K_TOTAL * 2) + half * 32;
    const uint32_t so = (uint32_t)r * PITCH + half * 32;

    // ldmatrix lane offsets (validated fragment math)
    const uint32_t aoff = (uint32_t)(lane & 15) * PITCH + (lane >> 4) * 16;
    const uint32_t boff = (uint32_t)((lane & 7) + ((lane >> 4) << 3)) * PITCH
                        + ((lane >> 3) & 1) * 16;

    float acc[2][8][4];
#pragma unroll
    for (int f = 0; f < 2; f++)
#pragma unroll
        for (int j = 0; j < 8; j++)
#pragma unroll
            for (int c = 0; c < 4; c++) acc[f][j][c] = 0.0f;

#define FILL(s, kt) do {                                                  \
        uint32_t b_ = sb + (uint32_t)(s) * STAGE_BYTES + so;              \
        size_t   o_ = (size_t)(kt) * 64;                                  \
        cp16(b_,                gA + o_);                                 \
        cp16(b_ + 16,           gA + o_ + 16);                            \
        cp16(b_ + A_TILE_B,      gB + o_);                                \
        cp16(b_ + A_TILE_B + 16, gB + o_ + 16);                           \
    } while (0)

    // prologue: stages 0..2
#pragma unroll
    for (int p = 0; p < STAGES - 1; p++) {
        FILL(p, p);
        asm volatile("cp.async.commit_group;" ::: "memory");
    }

#pragma unroll 4
    for (int kt = 0; kt < NKT; kt++) {
        const int s = kt & (STAGES - 1);

        asm volatile("cp.async.wait_group %0;" :: "n"(STAGES - 2) : "memory");
        __syncthreads();

        if (kt + STAGES - 1 < NKT) {
            FILL((kt + STAGES - 1) & (STAGES - 1), kt + STAGES - 1);
        }
        asm volatile("cp.async.commit_group;" ::: "memory");

        const uint32_t stA = sb + (uint32_t)s * STAGE_BYTES;
        const uint32_t stB = stA + A_TILE_B;

#pragma unroll
        for (int h = 0; h < 2; h++) {              // two k16 halves of BK=32
            uint32_t af[2][4], bq[4][4];
#pragma unroll
            for (int f = 0; f < 2; f++)
                ldsm4(af[f], stA + (uint32_t)(warp_m + 16 * f) * PITCH + aoff + h * 32);
#pragma unroll
            for (int g = 0; g < 4; g++)
                ldsm4(bq[g], stB + (uint32_t)(warp_n + 16 * g) * PITCH + boff + h * 32);
#pragma unroll
            for (int f = 0; f < 2; f++)
#pragma unroll
                for (int j = 0; j < 8; j++)
                    mma16816(acc[f][j], af[f], &bq[j >> 1][(j & 1) * 2]);
        }
    }
#undef FILL

    // ---------------- epilogue: smem staging, fused scale/bias, float4 stores ----------------
    __syncthreads();                                // stage buffers free
    float* sf = (float*)smem;                       // 128 x 132 f32 = 67584 B
    {
        const int qr = lane >> 2;                   // row within 8
        const int qc = (lane & 3) * 2;              // col pair
#pragma unroll
        for (int f = 0; f < 2; f++)
#pragma unroll
            for (int j = 0; j < 8; j++) {
                float* p0 = sf + (size_t)(warp_m + 16 * f + qr) * LDC + warp_n + 8 * j + qc;
                p0[0] = acc[f][j][0];
                p0[1] = acc[f][j][1];
                float* p1 = p0 + 8 * LDC;
                p1[0] = acc[f][j][2];
                p1[1] = acc[f][j][3];
            }
    }
    __syncthreads();

#pragma unroll 4
    for (int i = 0; i < 16; i++) {                  // 128 rows x 32 float4, 256 threads
        const int lin = i * 256 + tid;
        const int rr = lin >> 5;
        const int c4 = (lin & 31) * 4;
        float4 v4 = *reinterpret_cast<const float4*>(sf + (size_t)rr * LDC + c4);
        const float4 s4 = *reinterpret_cast<const float4*>(sc + n0 + c4);
        const float4 b4 = *reinterpret_cast<const float4*>(bi + n0 + c4);
        v4.x = fmaf(v4.x, s4.x, b4.x);
        v4.y = fmaf(v4.y, s4.y, b4.y);
        v4.z = fmaf(v4.z, s4.z, b4.z);
        v4.w = fmaf(v4.w, s4.w, b4.w);
        *reinterpret_cast<float4*>(out + (size_t)(m0 + rr) * N_TOTAL + n0 + c4) = v4;
    }
}

// ---------------- launch ----------------
extern "C" void kernel_launch(void* const* d_in, const int* in_sizes, int n_in,
                              void* d_out, int out_size) {
    // x = 16777216 f32, qw = 67108864 int32 (promoted int8), scale/bias = 16384 each.
    int i_x = -1, big[2] = {-1, -1}, nbig = 0, smalls[2] = {-1, -1}, nsmall = 0;
    for (int i = 0; i < n_in; i++) {
        if (in_sizes[i] == 16777216) i_x = i;
        else if (in_sizes[i] == 67108864) { if (nbig < 2) big[nbig] = i; nbig++; }
        else { if (nsmall < 2) smalls[nsmall] = i; nsmall++; }
    }
    const float* x; const int* qw;
    if (i_x >= 0 && nbig >= 1) { x = (const float*)d_in[i_x]; qw = (const int*)d_in[big[0]]; }
    else if (nbig == 2)        { x = (const float*)d_in[big[0]]; qw = (const int*)d_in[big[1]]; }
    else                       { x = (const float*)d_in[0]; qw = (const int*)d_in[1]; }
    const float* scale = (nsmall >= 1) ? (const float*)d_in[smalls[0]] : (const float*)d_in[2];
    const float* bias  = (nsmall >= 2) ? (const float*)d_in[smalls[1]] : (const float*)d_in[3];
    float* out = (float*)d_out;

    // merged pre-pass: 2 launches per call -> ncu -s 5 lands on k_gemm
    k_conv<<<(unsigned)(XBLOCKS + WBLOCKS), 256>>>(x, qw);

    cudaFuncSetAttribute(k_gemm, cudaFuncAttributeMaxDynamicSharedMemorySize, SMEM_TOTAL);
    dim3 grid(M_TOTAL / BM, N_TOTAL / BN);   // (32, 128), M fastest
    k_gemm<<<grid, 256, SMEM_TOTAL>>>(scale, bias, out);
}